// round 5
// baseline (speedup 1.0000x reference)
#include <cuda_runtime.h>
#include <cuda_bf16.h>
#include <math.h>
#include <stdint.h>

// ---------------- problem constants ----------------
#define E_DIM 512
#define H_HEADS 8
#define HEAD_DIM 64
#define L_LAYERS 2
#define FF_DIM 2048
#define CHUNK 40
#define OVERLAP 5
#define EXT 50
#define SLIDE 30
#define TOPK 3
#define B_BATCH 8
#define Q_LEN 30
#define D_LEN 2000
#define NK 11
#define C_CHUNKS 50            // (2020-50)/40+1
#define DOC_M (400*50)         // 20000 doc rows
#define QRY_M (8*30)           // 240 query rows
#define TOT_M (DOC_M + QRY_M)  // 20240 combined rows
#define NWIN 986               // (2000-30)/2+1

// ---------------- scratch (device globals; no allocation allowed) ----------------
__device__ float g_X  [TOT_M * E_DIM];
__device__ float g_QKV[TOT_M * 3 * E_DIM];
__device__ float g_O  [TOT_M * E_DIM];
__device__ float g_T  [TOT_M * E_DIM];
__device__ float g_F1 [TOT_M * FF_DIM];
__device__ float g_SEQ[DOC_M * E_DIM];        // doc chunk raw seq (for mixer)
__device__ float g_CM [DOC_M];                // chunk masks (400x50)
__device__ float g_QN [QRY_M * E_DIM];        // normalized query reps
__device__ float g_DN [B_BATCH * D_LEN * E_DIM]; // normalized doc reps
__device__ float g_MIN[B_BATCH * D_LEN];      // m_in * packed
__device__ float g_ACTS[(size_t)B_BATCH * Q_LEN * D_LEN * NK];
__device__ float g_SCORE[B_BATCH * NWIN];

// ---------------- SGEMM (NT): C[m,n] = sum_k A[m,k]*B[n,k] + bias[n] ----------------
// BK=16 double-buffered smem pipeline: prefetch tile t+1 into registers while
// computing tile t; one __syncthreads per 16-deep K-tile.
#define BM 128
#define BN 128
#define BKK 16
__global__ void __launch_bounds__(256) sgemm_nt_kernel(
    const float* __restrict__ A, const float* __restrict__ Bm,
    const float* __restrict__ bias, float* __restrict__ C,
    int M, int N, int K, int relu)
{
    __shared__ float As[2][BKK][BM];
    __shared__ float Bs[2][BKK][BN];
    int tid = threadIdx.x;
    int tx = tid & 15, ty = tid >> 4;
    int m0 = blockIdx.y * BM;
    int n0 = blockIdx.x * BN;

    float acc[8][8];
#pragma unroll
    for (int i = 0; i < 8; i++)
#pragma unroll
        for (int j = 0; j < 8; j++) acc[i][j] = 0.f;

    int lr = tid >> 1;          // 0..127 (row within tile)
    int lk = (tid & 1) * 8;     // 0 or 8 (k-offset; 8 floats = 2 float4 per thread)
    int arow = m0 + lr;
    const float* Aptr = A + (size_t)arow * K + lk;
    const float* Bptr = Bm + (size_t)(n0 + lr) * K + lk;
    bool avalid = (arow < M);

    // ---- load tile 0 into buffer 0 ----
    {
        float4 a0 = make_float4(0.f, 0.f, 0.f, 0.f);
        float4 a1 = make_float4(0.f, 0.f, 0.f, 0.f);
        if (avalid) {
            a0 = *(const float4*)(Aptr);
            a1 = *(const float4*)(Aptr + 4);
        }
        float4 b0 = *(const float4*)(Bptr);
        float4 b1 = *(const float4*)(Bptr + 4);
        As[0][lk + 0][lr] = a0.x; As[0][lk + 1][lr] = a0.y;
        As[0][lk + 2][lr] = a0.z; As[0][lk + 3][lr] = a0.w;
        As[0][lk + 4][lr] = a1.x; As[0][lk + 5][lr] = a1.y;
        As[0][lk + 6][lr] = a1.z; As[0][lk + 7][lr] = a1.w;
        Bs[0][lk + 0][lr] = b0.x; Bs[0][lk + 1][lr] = b0.y;
        Bs[0][lk + 2][lr] = b0.z; Bs[0][lk + 3][lr] = b0.w;
        Bs[0][lk + 4][lr] = b1.x; Bs[0][lk + 5][lr] = b1.y;
        Bs[0][lk + 6][lr] = b1.z; Bs[0][lk + 7][lr] = b1.w;
    }
    __syncthreads();

    int ntiles = K / BKK;
    for (int t = 0; t < ntiles; t++) {
        int cur = t & 1;
        int nxt = cur ^ 1;
        float4 a0 = make_float4(0.f, 0.f, 0.f, 0.f);
        float4 a1 = make_float4(0.f, 0.f, 0.f, 0.f);
        float4 b0 = make_float4(0.f, 0.f, 0.f, 0.f);
        float4 b1 = make_float4(0.f, 0.f, 0.f, 0.f);
        bool have_next = (t + 1 < ntiles);
        if (have_next) {
            int koff = (t + 1) * BKK;
            if (avalid) {
                a0 = *(const float4*)(Aptr + koff);
                a1 = *(const float4*)(Aptr + koff + 4);
            }
            b0 = *(const float4*)(Bptr + koff);
            b1 = *(const float4*)(Bptr + koff + 4);
        }
#pragma unroll
        for (int kk = 0; kk < BKK; kk++) {
            float a[8], b[8];
#pragma unroll
            for (int i = 0; i < 8; i++) a[i] = As[cur][kk][ty * 8 + i];
#pragma unroll
            for (int j = 0; j < 8; j++) b[j] = Bs[cur][kk][tx * 8 + j];
#pragma unroll
            for (int i = 0; i < 8; i++)
#pragma unroll
                for (int j = 0; j < 8; j++)
                    acc[i][j] = fmaf(a[i], b[j], acc[i][j]);
        }
        if (have_next) {
            As[nxt][lk + 0][lr] = a0.x; As[nxt][lk + 1][lr] = a0.y;
            As[nxt][lk + 2][lr] = a0.z; As[nxt][lk + 3][lr] = a0.w;
            As[nxt][lk + 4][lr] = a1.x; As[nxt][lk + 5][lr] = a1.y;
            As[nxt][lk + 6][lr] = a1.z; As[nxt][lk + 7][lr] = a1.w;
            Bs[nxt][lk + 0][lr] = b0.x; Bs[nxt][lk + 1][lr] = b0.y;
            Bs[nxt][lk + 2][lr] = b0.z; Bs[nxt][lk + 3][lr] = b0.w;
            Bs[nxt][lk + 4][lr] = b1.x; Bs[nxt][lk + 5][lr] = b1.y;
            Bs[nxt][lk + 6][lr] = b1.z; Bs[nxt][lk + 7][lr] = b1.w;
        }
        __syncthreads();
    }

#pragma unroll
    for (int i = 0; i < 8; i++) {
        int m = m0 + ty * 8 + i;
        if (m >= M) break;
#pragma unroll
        for (int j = 0; j < 8; j++) {
            int n = n0 + tx * 8 + j;
            float v = acc[i][j] + bias[n];
            if (relu) v = fmaxf(v, 0.f);
            C[(size_t)m * N + n] = v;
        }
    }
}

// ---------------- attention: one block per (n,h) ----------------
// QKV/O pointers are pre-offset to the segment start (doc or query rows).
#define MAXS 50
__global__ void __launch_bounds__(256) attn_kernel(
    const float* __restrict__ QKV, const float* __restrict__ mask,
    float* __restrict__ O, int S)
{
    __shared__ float qs[MAXS][65], ks[MAXS][65], vs[MAXS][65];
    __shared__ float msk[MAXS];
    __shared__ float pbuf[8][MAXS];
    int blk = blockIdx.x;
    int n = blk >> 3;
    int h = blk & 7;
    int tid = threadIdx.x;
    const float* base = QKV + (size_t)n * S * (3 * E_DIM) + h * HEAD_DIM;
    for (int idx = tid; idx < S * HEAD_DIM; idx += 256) {
        int s = idx >> 6, e = idx & 63;
        const float* row = base + (size_t)s * (3 * E_DIM);
        qs[s][e] = row[e];
        ks[s][e] = row[E_DIM + e];
        vs[s][e] = row[2 * E_DIM + e];
    }
    for (int j = tid; j < S; j += 256) msk[j] = mask[n * S + j];
    __syncthreads();

    int warp = tid >> 5, lane = tid & 31;
    for (int i = warp; i < S; i += 8) {
        float sc0 = -INFINITY, sc1 = -INFINITY;
        if (lane < S) {
            float d = 0.f;
#pragma unroll
            for (int e = 0; e < 64; e++) d = fmaf(qs[i][e], ks[lane][e], d);
            d *= 0.125f;
            if (!(msk[lane] > 0.f)) d = -1e9f;
            sc0 = d;
        }
        if (lane + 32 < S) {
            float d = 0.f;
#pragma unroll
            for (int e = 0; e < 64; e++) d = fmaf(qs[i][e], ks[lane + 32][e], d);
            d *= 0.125f;
            if (!(msk[lane + 32] > 0.f)) d = -1e9f;
            sc1 = d;
        }
        float m = fmaxf(sc0, sc1);
        for (int o = 16; o > 0; o >>= 1) m = fmaxf(m, __shfl_xor_sync(0xffffffffu, m, o));
        float e0 = (lane < S) ? expf(sc0 - m) : 0.f;
        float e1 = (lane + 32 < S) ? expf(sc1 - m) : 0.f;
        float ssum = e0 + e1;
        for (int o = 16; o > 0; o >>= 1) ssum += __shfl_xor_sync(0xffffffffu, ssum, o);
        float inv = 1.f / ssum;
        if (lane < S) pbuf[warp][lane] = e0 * inv;
        if (lane + 32 < S) pbuf[warp][lane + 32] = e1 * inv;
        __syncwarp();
        float o0 = 0.f, o1 = 0.f;
        for (int j = 0; j < S; j++) {
            float p = pbuf[warp][j];
            o0 = fmaf(p, vs[j][lane], o0);
            o1 = fmaf(p, vs[j][lane + 32], o1);
        }
        float* orow = O + ((size_t)n * S + i) * E_DIM + h * HEAD_DIM;
        orow[lane] = o0;
        orow[lane + 32] = o1;
    }
}

// ---------------- layernorm: X = LN(X + T) ----------------
__global__ void __launch_bounds__(128) ln_kernel(
    float* __restrict__ X, const float* __restrict__ T,
    const float* __restrict__ g, const float* __restrict__ b)
{
    int row = blockIdx.x;
    int tid = threadIdx.x;
    __shared__ float red1[4], red2[4];
    float4 x4 = *(const float4*)(X + (size_t)row * E_DIM + tid * 4);
    float4 t4 = *(const float4*)(T + (size_t)row * E_DIM + tid * 4);
    float v0 = x4.x + t4.x, v1 = x4.y + t4.y, v2 = x4.z + t4.z, v3 = x4.w + t4.w;
    float s = v0 + v1 + v2 + v3;
    for (int o = 16; o > 0; o >>= 1) s += __shfl_xor_sync(0xffffffffu, s, o);
    if ((tid & 31) == 0) red1[tid >> 5] = s;
    __syncthreads();
    float mean = (red1[0] + red1[1] + red1[2] + red1[3]) * (1.f / 512.f);
    float d0 = v0 - mean, d1 = v1 - mean, d2 = v2 - mean, d3 = v3 - mean;
    float vsum = d0 * d0 + d1 * d1 + d2 * d2 + d3 * d3;
    for (int o = 16; o > 0; o >>= 1) vsum += __shfl_xor_sync(0xffffffffu, vsum, o);
    if ((tid & 31) == 0) red2[tid >> 5] = vsum;
    __syncthreads();
    float var = (red2[0] + red2[1] + red2[2] + red2[3]) * (1.f / 512.f);
    float inv = 1.f / sqrtf(var + 1e-5f);
    float4 g4 = *(const float4*)(g + tid * 4);
    float4 b4 = *(const float4*)(b + tid * 4);
    float4 out;
    out.x = d0 * inv * g4.x + b4.x;
    out.y = d1 * inv * g4.y + b4.y;
    out.z = d2 * inv * g4.z + b4.z;
    out.w = d3 * inv * g4.w + b4.w;
    *(float4*)(X + (size_t)row * E_DIM + tid * 4) = out;
}

// ---------------- builders ----------------
// query rows live at X + DOC_M*E_DIM
__global__ void build_query_kernel(const float* __restrict__ qe,
                                   const float* __restrict__ pos_q, float* __restrict__ Xq)
{
    int i = blockIdx.x * 256 + threadIdx.x;
    if (i < QRY_M * E_DIM) {
        int e = i & 511;
        int r = i >> 9;
        int s = r % Q_LEN;
        Xq[i] = qe[i] + pos_q[s * E_DIM + e];
    }
}

__global__ void build_doc_kernel(const float* __restrict__ de, const float* __restrict__ dm,
                                 const float* __restrict__ pos_d,
                                 float* __restrict__ SEQ, float* __restrict__ X,
                                 float* __restrict__ CM)
{
    int bc = blockIdx.x;             // 0..399
    int b = bc / C_CHUNKS, c = bc % C_CHUNKS;
    int tid = threadIdx.x;
    for (int idx = tid; idx < EXT * E_DIM; idx += 256) {
        int j = idx >> 9, e = idx & 511;
        int src = c * CHUNK + j - OVERLAP;
        float v = (src >= 0 && src < D_LEN) ? de[((size_t)b * D_LEN + src) * E_DIM + e] : 0.f;
        size_t o = ((size_t)bc * EXT + j) * E_DIM + e;
        SEQ[o] = v;
        X[o] = v + pos_d[idx];
    }
    for (int j = tid; j < EXT; j += 256) {
        int src = c * CHUNK + j - OVERLAP;
        CM[bc * EXT + j] = (src >= 0 && src < D_LEN) ? dm[b * D_LEN + src] : 0.f;
    }
}

__global__ void build_min_kernel(const float* __restrict__ CM, float* __restrict__ MIN)
{
    int bc = blockIdx.x;
    int b = bc / C_CHUNKS, c = bc % C_CHUNKS;
    __shared__ float psum;
    if (threadIdx.x == 0) {
        float s = 0.f;
        for (int d = 0; d < CHUNK; d++) s += CM[bc * EXT + OVERLAP + d];
        psum = s;
    }
    __syncthreads();
    float pk = (psum != 0.f) ? 1.f : 0.f;
    if (threadIdx.x < CHUNK) {
        MIN[(size_t)b * D_LEN + c * CHUNK + threadIdx.x] =
            CM[bc * EXT + OVERLAP + threadIdx.x] * pk;
    }
}

// ---------------- fused mix + mask + L2-normalize ----------------
__device__ __forceinline__ float blk128_sum(float v, float* red)
{
    for (int o = 16; o > 0; o >>= 1) v += __shfl_xor_sync(0xffffffffu, v, o);
    if ((threadIdx.x & 31) == 0) red[threadIdx.x >> 5] = v;
    __syncthreads();
    return red[0] + red[1] + red[2] + red[3];
}

__global__ void __launch_bounds__(128) mixnorm_q_kernel(
    const float* __restrict__ qe, const float* __restrict__ Xq,
    const float* __restrict__ qm, const float* __restrict__ mixer,
    float* __restrict__ QN)
{
    __shared__ float red[4];
    int r = blockIdx.x;              // 0..239
    float mx = mixer[0];
    float mk = qm[r];
    size_t off = (size_t)r * E_DIM + threadIdx.x * 4;
    float4 s4 = *(const float4*)(qe + off);
    float4 x4 = *(const float4*)(Xq + off);
    float4 v;
    v.x = (mx * s4.x + (1.f - mx) * x4.x) * mk;
    v.y = (mx * s4.y + (1.f - mx) * x4.y) * mk;
    v.z = (mx * s4.z + (1.f - mx) * x4.z) * mk;
    v.w = (mx * s4.w + (1.f - mx) * x4.w) * mk;
    float ss = v.x * v.x + v.y * v.y + v.z * v.z + v.w * v.w;
    float tot = blk128_sum(ss, red);
    float inv = 1.f / (sqrtf(tot) + 1e-13f);
    float4 o = make_float4(v.x * inv, v.y * inv, v.z * inv, v.w * inv);
    *(float4*)(QN + off) = o;
}

__global__ void __launch_bounds__(128) mixnorm_d_kernel(
    const float* __restrict__ SEQ, const float* __restrict__ X,
    const float* __restrict__ CM, const float* __restrict__ mixer,
    float* __restrict__ DN)
{
    __shared__ float red[4];
    int r = blockIdx.x;              // b*2000 + p
    int b = r / D_LEN, p = r % D_LEN;
    int c = p / CHUNK, d = p % CHUNK;
    int srow = (b * C_CHUNKS + c) * EXT + OVERLAP + d;
    float mx = mixer[0];
    float mk = CM[srow];
    size_t off = (size_t)srow * E_DIM + threadIdx.x * 4;
    float4 s4 = *(const float4*)(SEQ + off);
    float4 x4 = *(const float4*)(X + off);
    float4 v;
    v.x = (mx * s4.x + (1.f - mx) * x4.x) * mk;
    v.y = (mx * s4.y + (1.f - mx) * x4.y) * mk;
    v.z = (mx * s4.z + (1.f - mx) * x4.z) * mk;
    v.w = (mx * s4.w + (1.f - mx) * x4.w) * mk;
    float ss = v.x * v.x + v.y * v.y + v.z * v.z + v.w * v.w;
    float tot = blk128_sum(ss, red);
    float inv = 1.f / (sqrtf(tot) + 1e-13f);
    float4 o = make_float4(v.x * inv, v.y * inv, v.z * inv, v.w * inv);
    *(float4*)(DN + (size_t)r * E_DIM + threadIdx.x * 4) = o;
}

// ---------------- cos + RBF kernels -> ACTS[b][q][p][k] ----------------
__global__ void __launch_bounds__(256) acts_kernel(
    const float* __restrict__ QN, const float* __restrict__ DN,
    const float* __restrict__ MIN, const float* __restrict__ mu,
    const float* __restrict__ sigma, float* __restrict__ ACTS)
{
    __shared__ float dn_s[E_DIM];
    __shared__ float mus[NK], sg[NK];
    int r = blockIdx.x;              // b*2000 + p
    int b = r / D_LEN;
    int p = r % D_LEN;
    int tid = threadIdx.x;
    for (int e = tid; e < E_DIM; e += 256) dn_s[e] = DN[(size_t)r * E_DIM + e];
    if (tid < NK) { mus[tid] = mu[tid]; sg[tid] = 0.5f / (sigma[tid] * sigma[tid]); }
    __syncthreads();
    float mn = MIN[r];
    int warp = tid >> 5, lane = tid & 31;
    for (int q = warp; q < Q_LEN; q += 8) {
        const float* qrow = QN + ((size_t)b * Q_LEN + q) * E_DIM;
        float d = 0.f;
        for (int e = lane; e < E_DIM; e += 32) d = fmaf(qrow[e], dn_s[e], d);
        for (int o = 16; o > 0; o >>= 1) d += __shfl_xor_sync(0xffffffffu, d, o);
        if (lane < NK) {
            float df = d - mus[lane];
            float val = expf(-df * df * sg[lane]) * mn;
            ACTS[(((size_t)b * Q_LEN + q) * D_LEN + p) * NK + lane] = val;
        }
    }
}

// ---------------- sliding-window scores ----------------
__global__ void __launch_bounds__(352) score_kernel(
    const float* __restrict__ ACTS, const float* __restrict__ MIN,
    const float* __restrict__ qm, const float* __restrict__ dense_w,
    float* __restrict__ SCORE)
{
    int w = blockIdx.x;              // 0..985
    int b = blockIdx.y;
    int tid = threadIdx.x;
    __shared__ float sat_s[Q_LEN * NK];
    __shared__ float red[NK];
    __shared__ float Lsh;
    if (tid == 0) {
        float L = 0.f;
        for (int j = 0; j < SLIDE; j++)
            if (MIN[(size_t)b * D_LEN + 2 * w + j] != 0.f) L += 1.f;
        Lsh = L;
    }
    __syncthreads();
    if (tid < Q_LEN * NK) {
        int q = tid / NK, k = tid % NK;
        size_t base = (((size_t)b * Q_LEN + q) * D_LEN + 2 * w) * NK + k;
        float pkq = 0.f;
#pragma unroll
        for (int j = 0; j < SLIDE; j++) pkq += ACTS[base + (size_t)j * NK];
        float sat = logf(fmaxf(pkq, 1e-10f)) * qm[b * Q_LEN + q] * (Lsh > 0.f ? 1.f : 0.f);
        sat_s[tid] = sat;
    }
    __syncthreads();
    if (tid < NK) {
        float pk = 0.f;
        for (int q = 0; q < Q_LEN; q++) pk += sat_s[q * NK + tid];
        red[tid] = pk * dense_w[tid];
    }
    __syncthreads();
    if (tid == 0) {
        float s = 0.f;
        for (int k = 0; k < NK; k++) s += red[k];
        if (s == 0.f) s = -9000.f;
        SCORE[b * NWIN + w] = s;
    }
}

// ---------------- topk with suppression + final score ----------------
__global__ void topk_kernel(const float* __restrict__ SCORE,
                            const float* __restrict__ cs, float* __restrict__ out)
{
    int b = blockIdx.x;
    __shared__ float sc[NWIN];
    __shared__ float work[NWIN];
    for (int i = threadIdx.x; i < NWIN; i += blockDim.x) {
        float v = SCORE[b * NWIN + i];
        sc[i] = v;
        work[i] = v;
    }
    __syncthreads();
    if (threadIdx.x == 0) {
        int tops[TOPK];
        for (int t = 0; t < TOPK; t++) {
            int best = 0; float bv = work[0];
            for (int i = 1; i < NWIN; i++)
                if (work[i] > bv) { bv = work[i]; best = i; }
            tops[t] = best;
            for (int i = 0; i < NWIN; i++) {
                int d = i - best; if (d < 0) d = -d;
                if (d < 15) work[i] = -10001.f - (float)t;
            }
        }
        float acc = 0.f;
        const int offs[5] = {0, -1, 1, -2, 2};
        for (int oi = 0; oi < 5; oi++)
            for (int t = 0; t < TOPK; t++) {
                int idx = tops[t] + offs[oi];
                if (idx < 0) idx = 0;
                if (idx > NWIN - 1) idx = NWIN - 1;
                float v = sc[idx];
                if (v <= -9000.f) v = 0.f;
                acc += v * cs[oi * TOPK + t];
            }
        out[b] = acc;
    }
}

// ---------------- host orchestration ----------------
extern "C" void kernel_launch(void* const* d_in, const int* in_sizes, int n_in,
                              void* d_out, int out_size)
{
    const float* qe      = (const float*)d_in[0];
    const float* de      = (const float*)d_in[1];
    const float* qm      = (const float*)d_in[2];
    const float* dm      = (const float*)d_in[3];
    const float* pos_q   = (const float*)d_in[4];
    const float* pos_d   = (const float*)d_in[5];
    const float* Wqkv    = (const float*)d_in[6];
    const float* bqkv    = (const float*)d_in[7];
    const float* Wo      = (const float*)d_in[8];
    const float* bo      = (const float*)d_in[9];
    const float* ln1g    = (const float*)d_in[10];
    const float* ln1b    = (const float*)d_in[11];
    const float* Wff1    = (const float*)d_in[12];
    const float* bff1    = (const float*)d_in[13];
    const float* Wff2    = (const float*)d_in[14];
    const float* bff2    = (const float*)d_in[15];
    const float* ln2g    = (const float*)d_in[16];
    const float* ln2b    = (const float*)d_in[17];
    const float* mixer   = (const float*)d_in[18];
    const float* dense_w = (const float*)d_in[19];
    const float* chunksc = (const float*)d_in[20];
    const float* mu      = (const float*)d_in[21];
    const float* sigma   = (const float*)d_in[22];
    (void)in_sizes; (void)n_in; (void)out_size;

    float *X, *QKV, *O, *T, *F1, *SEQ, *CM, *QN, *DN, *MIN, *ACTS, *SCORE;
    cudaGetSymbolAddress((void**)&X, g_X);
    cudaGetSymbolAddress((void**)&QKV, g_QKV);
    cudaGetSymbolAddress((void**)&O, g_O);
    cudaGetSymbolAddress((void**)&T, g_T);
    cudaGetSymbolAddress((void**)&F1, g_F1);
    cudaGetSymbolAddress((void**)&SEQ, g_SEQ);
    cudaGetSymbolAddress((void**)&CM, g_CM);
    cudaGetSymbolAddress((void**)&QN, g_QN);
    cudaGetSymbolAddress((void**)&DN, g_DN);
    cudaGetSymbolAddress((void**)&MIN, g_MIN);
    cudaGetSymbolAddress((void**)&ACTS, g_ACTS);
    cudaGetSymbolAddress((void**)&SCORE, g_SCORE);

    // ---- build combined input: rows [0,DOC_M) = doc chunks, [DOC_M,TOT_M) = query ----
    build_doc_kernel<<<B_BATCH * C_CHUNKS, 256>>>(de, dm, pos_d, SEQ, X, CM);
    build_query_kernel<<<(QRY_M * E_DIM + 255) / 256, 256>>>(
        qe, pos_q, X + (size_t)DOC_M * E_DIM);

    // ---- single fused transformer over TOT_M rows ----
    {
        int M = TOT_M;
        int gy = (M + BM - 1) / BM;
        for (int l = 0; l < L_LAYERS; l++) {
            const float* Wq  = Wqkv + (size_t)l * 3 * E_DIM * E_DIM;
            const float* bq  = bqkv + (size_t)l * 3 * E_DIM;
            const float* Wol = Wo   + (size_t)l * E_DIM * E_DIM;
            const float* bol = bo   + (size_t)l * E_DIM;
            const float* W1l = Wff1 + (size_t)l * FF_DIM * E_DIM;
            const float* b1l = bff1 + (size_t)l * FF_DIM;
            const float* W2l = Wff2 + (size_t)l * E_DIM * FF_DIM;
            const float* b2l = bff2 + (size_t)l * E_DIM;

            sgemm_nt_kernel<<<dim3(3 * E_DIM / BN, gy), 256>>>(
                X, Wq, bq, QKV, M, 3 * E_DIM, E_DIM, 0);
            // doc segment: 400 seqs of S=50
            attn_kernel<<<B_BATCH * C_CHUNKS * H_HEADS, 256>>>(QKV, CM, O, EXT);
            // query segment: 8 seqs of S=30
            attn_kernel<<<B_BATCH * H_HEADS, 256>>>(
                QKV + (size_t)DOC_M * 3 * E_DIM, qm, O + (size_t)DOC_M * E_DIM, Q_LEN);
            sgemm_nt_kernel<<<dim3(E_DIM / BN, gy), 256>>>(
                O, Wol, bol, T, M, E_DIM, E_DIM, 0);
            ln_kernel<<<M, 128>>>(X, T, ln1g + (size_t)l * E_DIM, ln1b + (size_t)l * E_DIM);
            sgemm_nt_kernel<<<dim3(FF_DIM / BN, gy), 256>>>(
                X, W1l, b1l, F1, M, FF_DIM, E_DIM, 1);
            sgemm_nt_kernel<<<dim3(E_DIM / BN, gy), 256>>>(
                F1, W2l, b2l, T, M, E_DIM, FF_DIM, 0);
            ln_kernel<<<M, 128>>>(X, T, ln2g + (size_t)l * E_DIM, ln2b + (size_t)l * E_DIM);
        }
    }

    // ---- mix + normalize ----
    mixnorm_q_kernel<<<QRY_M, 128>>>(qe, X + (size_t)DOC_M * E_DIM, qm, mixer, QN);
    mixnorm_d_kernel<<<B_BATCH * D_LEN, 128>>>(SEQ, X, CM, mixer, DN);
    build_min_kernel<<<B_BATCH * C_CHUNKS, 64>>>(CM, MIN);

    // ---- matching / scoring ----
    acts_kernel<<<B_BATCH * D_LEN, 256>>>(QN, DN, MIN, mu, sigma, ACTS);
    score_kernel<<<dim3(NWIN, B_BATCH), 352>>>(ACTS, MIN, qm, dense_w, SCORE);
    topk_kernel<<<B_BATCH, 256>>>(SCORE, chunksc, (float*)d_out);
}

// round 8
// speedup vs baseline: 2.6752x; 2.6752x over previous
#include <cuda_runtime.h>
#include <cuda_bf16.h>
#include <math.h>
#include <stdint.h>

// ---------------- problem constants ----------------
#define E_DIM 512
#define H_HEADS 8
#define HEAD_DIM 64
#define L_LAYERS 2
#define FF_DIM 2048
#define CHUNK 40
#define OVERLAP 5
#define EXT 50
#define SLIDE 30
#define TOPK 3
#define B_BATCH 8
#define Q_LEN 30
#define D_LEN 2000
#define NK 11
#define C_CHUNKS 50            // (2020-50)/40+1
#define DOC_M (400*50)         // 20000 doc rows
#define QRY_M (8*30)           // 240 query rows
#define TOT_M (DOC_M + QRY_M)  // 20240 combined rows
#define NWIN 986               // (2000-30)/2+1

// ---------------- scratch (device globals; no allocation allowed) ----------------
__device__ float g_X  [TOT_M * E_DIM];
__device__ float g_QKV[TOT_M * 3 * E_DIM];
__device__ float g_O  [TOT_M * E_DIM];
__device__ float g_T  [TOT_M * E_DIM];
__device__ float g_F1 [TOT_M * FF_DIM];
__device__ float g_SEQ[DOC_M * E_DIM];        // doc chunk raw seq (for mixer)
__device__ float g_CM [DOC_M];                // chunk masks (400x50)
__device__ float g_QN [QRY_M * E_DIM];        // normalized query reps
__device__ float g_DN [B_BATCH * D_LEN * E_DIM]; // normalized doc reps
__device__ float g_MIN[B_BATCH * D_LEN];      // m_in * packed
__device__ float g_ACTS[(size_t)B_BATCH * Q_LEN * D_LEN * NK];
__device__ float g_SCORE[B_BATCH * NWIN];

// ---------------- tf32 tensor-core GEMM (NT): C[m,n] = sum_k A[m,k]*W[n,k] + bias[n] ----
// mma.sync.m16n8k8.tf32. BM=BN=128, BK=16, 256 threads = 8 warps (4 m x 2 n),
// warp tile 32x64. Smem k-major, row stride 136 words (136%32==8) so the
// fragment gather (4 k-rows x 8 m/n-cols per LDS) is bank-conflict-free.
#define BM 128
#define BN 128
#define BK 16
#define BMP 136

__device__ __forceinline__ uint32_t f2tf32(float f) {
    uint32_t u;
    asm("cvt.rna.tf32.f32 %0, %1;" : "=r"(u) : "f"(f));
    return u;
}

__device__ __forceinline__ void mma_tf32(float* c, const uint32_t* a, const uint32_t* b) {
    asm volatile(
        "mma.sync.aligned.m16n8k8.row.col.f32.tf32.tf32.f32 "
        "{%0,%1,%2,%3}, {%4,%5,%6,%7}, {%8,%9}, {%0,%1,%2,%3};\n"
        : "+f"(c[0]), "+f"(c[1]), "+f"(c[2]), "+f"(c[3])
        : "r"(a[0]), "r"(a[1]), "r"(a[2]), "r"(a[3]), "r"(b[0]), "r"(b[1]));
}

__global__ void __launch_bounds__(256) gemm_tf32_nt(
    const float* __restrict__ A, const float* __restrict__ W,
    const float* __restrict__ bias, float* __restrict__ C,
    int M, int N, int K, int relu)
{
    __shared__ uint32_t As[2][BK][BMP];
    __shared__ uint32_t Bs[2][BK][BMP];
    int tid = threadIdx.x;
    int m0 = blockIdx.y * BM;
    int n0 = blockIdx.x * BN;

    // loader mapping: thread t loads row (t&127), k-half (t>>7)*8 (8 floats = 2 float4)
    int lr = tid & 127;
    int lk = (tid >> 7) * 8;
    int arow = m0 + lr;
    bool avalid = (arow < M);
    const float* Aptr = A + (size_t)arow * K + lk;
    const float* Wptr = W + (size_t)(n0 + lr) * K + lk;

    float acc[2][8][4];
#pragma unroll
    for (int mm = 0; mm < 2; mm++)
#pragma unroll
        for (int nn = 0; nn < 8; nn++)
#pragma unroll
            for (int r = 0; r < 4; r++) acc[mm][nn][r] = 0.f;

    // ---- load tile 0 ----
    {
        float4 a0 = make_float4(0.f, 0.f, 0.f, 0.f), a1 = a0;
        if (avalid) { a0 = *(const float4*)(Aptr); a1 = *(const float4*)(Aptr + 4); }
        float4 b0 = *(const float4*)(Wptr), b1 = *(const float4*)(Wptr + 4);
        float av[8] = {a0.x, a0.y, a0.z, a0.w, a1.x, a1.y, a1.z, a1.w};
        float bv[8] = {b0.x, b0.y, b0.z, b0.w, b1.x, b1.y, b1.z, b1.w};
#pragma unroll
        for (int i = 0; i < 8; i++) {
            As[0][lk + i][lr] = f2tf32(av[i]);
            Bs[0][lk + i][lr] = f2tf32(bv[i]);
        }
    }
    __syncthreads();

    int warpId = tid >> 5;
    int warpM = warpId >> 1;       // 0..3 -> m offset 32*warpM
    int warpN = warpId & 1;        // 0..1 -> n offset 64*warpN
    int lane = tid & 31;
    int gid = lane >> 2;           // 0..7
    int tig = lane & 3;            // 0..3

    int ntiles = K / BK;
    for (int t = 0; t < ntiles; t++) {
        int cur = t & 1, nxt = cur ^ 1;
        float4 pa0 = make_float4(0.f, 0.f, 0.f, 0.f), pa1 = pa0, pb0 = pa0, pb1 = pa0;
        bool have = (t + 1 < ntiles);
        if (have) {
            int ko = (t + 1) * BK;
            if (avalid) { pa0 = *(const float4*)(Aptr + ko); pa1 = *(const float4*)(Aptr + ko + 4); }
            pb0 = *(const float4*)(Wptr + ko);
            pb1 = *(const float4*)(Wptr + ko + 4);
        }
#pragma unroll
        for (int ks = 0; ks < BK; ks += 8) {
            uint32_t af[2][4];
#pragma unroll
            for (int mm = 0; mm < 2; mm++) {
                int mb = warpM * 32 + mm * 16 + gid;
                af[mm][0] = As[cur][ks + tig][mb];
                af[mm][1] = As[cur][ks + tig][mb + 8];
                af[mm][2] = As[cur][ks + tig + 4][mb];
                af[mm][3] = As[cur][ks + tig + 4][mb + 8];
            }
#pragma unroll
            for (int nn = 0; nn < 8; nn++) {
                uint32_t bf[2];
                int nb = warpN * 64 + nn * 8 + gid;
                bf[0] = Bs[cur][ks + tig][nb];
                bf[1] = Bs[cur][ks + tig + 4][nb];
                mma_tf32(acc[0][nn], af[0], bf);
                mma_tf32(acc[1][nn], af[1], bf);
            }
        }
        if (have) {
            float av[8] = {pa0.x, pa0.y, pa0.z, pa0.w, pa1.x, pa1.y, pa1.z, pa1.w};
            float bv[8] = {pb0.x, pb0.y, pb0.z, pb0.w, pb1.x, pb1.y, pb1.z, pb1.w};
#pragma unroll
            for (int i = 0; i < 8; i++) {
                As[nxt][lk + i][lr] = f2tf32(av[i]);
                Bs[nxt][lk + i][lr] = f2tf32(bv[i]);
            }
        }
        __syncthreads();
    }

    // ---- epilogue ----
#pragma unroll
    for (int mm = 0; mm < 2; mm++) {
        int r0 = m0 + warpM * 32 + mm * 16 + gid;
#pragma unroll
        for (int nn = 0; nn < 8; nn++) {
            int col = n0 + warpN * 64 + nn * 8 + 2 * tig;
            float bx = bias[col], by = bias[col + 1];
            if (r0 < M) {
                float vx = acc[mm][nn][0] + bx;
                float vy = acc[mm][nn][1] + by;
                if (relu) { vx = fmaxf(vx, 0.f); vy = fmaxf(vy, 0.f); }
                *(float2*)(C + (size_t)r0 * N + col) = make_float2(vx, vy);
            }
            if (r0 + 8 < M) {
                float vx = acc[mm][nn][2] + bx;
                float vy = acc[mm][nn][3] + by;
                if (relu) { vx = fmaxf(vx, 0.f); vy = fmaxf(vy, 0.f); }
                *(float2*)(C + (size_t)(r0 + 8) * N + col) = make_float2(vx, vy);
            }
        }
    }
}

// ---------------- attention: one block per (n,h) ----------------
// smem stride 68 floats (float4-aligned; lane*68 % 32 = lane*4 -> LDS.128
// conflict-free per quarter-warp). Dot loops read float4; accumulation order
// per element is unchanged (x,y,z,w sequential) so output is bit-identical.
#define MAXS 50
#define APAD 68
__global__ void __launch_bounds__(256) attn_kernel(
    const float* __restrict__ QKV, const float* __restrict__ mask,
    float* __restrict__ O, int S)
{
    __shared__ float qs[MAXS][APAD], ks[MAXS][APAD], vs[MAXS][APAD];
    __shared__ float msk[MAXS];
    __shared__ float pbuf[8][MAXS];
    int blk = blockIdx.x;
    int n = blk >> 3;
    int h = blk & 7;
    int tid = threadIdx.x;
    const float* base = QKV + (size_t)n * S * (3 * E_DIM) + h * HEAD_DIM;
    for (int idx = tid; idx < S * HEAD_DIM; idx += 256) {
        int s = idx >> 6, e = idx & 63;
        const float* row = base + (size_t)s * (3 * E_DIM);
        qs[s][e] = row[e];
        ks[s][e] = row[E_DIM + e];
        vs[s][e] = row[2 * E_DIM + e];
    }
    for (int j = tid; j < S; j += 256) msk[j] = mask[n * S + j];
    __syncthreads();

    int warp = tid >> 5, lane = tid & 31;
    for (int i = warp; i < S; i += 8) {
        const float4* q4 = (const float4*)qs[i];
        float sc0 = -INFINITY, sc1 = -INFINITY;
        if (lane < S) {
            const float4* k4 = (const float4*)ks[lane];
            float d = 0.f;
#pragma unroll
            for (int e = 0; e < 16; e++) {
                float4 qv = q4[e], kv = k4[e];
                d = fmaf(qv.x, kv.x, d);
                d = fmaf(qv.y, kv.y, d);
                d = fmaf(qv.z, kv.z, d);
                d = fmaf(qv.w, kv.w, d);
            }
            d *= 0.125f;
            if (!(msk[lane] > 0.f)) d = -1e9f;
            sc0 = d;
        }
        if (lane + 32 < S) {
            const float4* k4 = (const float4*)ks[lane + 32];
            float d = 0.f;
#pragma unroll
            for (int e = 0; e < 16; e++) {
                float4 qv = q4[e], kv = k4[e];
                d = fmaf(qv.x, kv.x, d);
                d = fmaf(qv.y, kv.y, d);
                d = fmaf(qv.z, kv.z, d);
                d = fmaf(qv.w, kv.w, d);
            }
            d *= 0.125f;
            if (!(msk[lane + 32] > 0.f)) d = -1e9f;
            sc1 = d;
        }
        float m = fmaxf(sc0, sc1);
        for (int o = 16; o > 0; o >>= 1) m = fmaxf(m, __shfl_xor_sync(0xffffffffu, m, o));
        float e0 = (lane < S) ? expf(sc0 - m) : 0.f;
        float e1 = (lane + 32 < S) ? expf(sc1 - m) : 0.f;
        float ssum = e0 + e1;
        for (int o = 16; o > 0; o >>= 1) ssum += __shfl_xor_sync(0xffffffffu, ssum, o);
        float inv = 1.f / ssum;
        if (lane < S) pbuf[warp][lane] = e0 * inv;
        if (lane + 32 < S) pbuf[warp][lane + 32] = e1 * inv;
        __syncwarp();
        float o0 = 0.f, o1 = 0.f;
        for (int j = 0; j < S; j++) {
            float p = pbuf[warp][j];
            o0 = fmaf(p, vs[j][lane], o0);
            o1 = fmaf(p, vs[j][lane + 32], o1);
        }
        float* orow = O + ((size_t)n * S + i) * E_DIM + h * HEAD_DIM;
        orow[lane] = o0;
        orow[lane + 32] = o1;
    }
}

// ---------------- layernorm: X = LN(X + T) ----------------
__global__ void __launch_bounds__(128) ln_kernel(
    float* __restrict__ X, const float* __restrict__ T,
    const float* __restrict__ g, const float* __restrict__ b)
{
    int row = blockIdx.x;
    int tid = threadIdx.x;
    __shared__ float red1[4], red2[4];
    float4 x4 = *(const float4*)(X + (size_t)row * E_DIM + tid * 4);
    float4 t4 = *(const float4*)(T + (size_t)row * E_DIM + tid * 4);
    float v0 = x4.x + t4.x, v1 = x4.y + t4.y, v2 = x4.z + t4.z, v3 = x4.w + t4.w;
    float s = v0 + v1 + v2 + v3;
    for (int o = 16; o > 0; o >>= 1) s += __shfl_xor_sync(0xffffffffu, s, o);
    if ((tid & 31) == 0) red1[tid >> 5] = s;
    __syncthreads();
    float mean = (red1[0] + red1[1] + red1[2] + red1[3]) * (1.f / 512.f);
    float d0 = v0 - mean, d1 = v1 - mean, d2 = v2 - mean, d3 = v3 - mean;
    float vsum = d0 * d0 + d1 * d1 + d2 * d2 + d3 * d3;
    for (int o = 16; o > 0; o >>= 1) vsum += __shfl_xor_sync(0xffffffffu, vsum, o);
    if ((tid & 31) == 0) red2[tid >> 5] = vsum;
    __syncthreads();
    float var = (red2[0] + red2[1] + red2[2] + red2[3]) * (1.f / 512.f);
    float inv = 1.f / sqrtf(var + 1e-5f);
    float4 g4 = *(const float4*)(g + tid * 4);
    float4 b4 = *(const float4*)(b + tid * 4);
    float4 out;
    out.x = d0 * inv * g4.x + b4.x;
    out.y = d1 * inv * g4.y + b4.y;
    out.z = d2 * inv * g4.z + b4.z;
    out.w = d3 * inv * g4.w + b4.w;
    *(float4*)(X + (size_t)row * E_DIM + tid * 4) = out;
}

// ---------------- builders ----------------
__global__ void build_query_kernel(const float* __restrict__ qe,
                                   const float* __restrict__ pos_q, float* __restrict__ Xq)
{
    int i = blockIdx.x * 256 + threadIdx.x;
    if (i < QRY_M * E_DIM) {
        int e = i & 511;
        int r = i >> 9;
        int s = r % Q_LEN;
        Xq[i] = qe[i] + pos_q[s * E_DIM + e];
    }
}

__global__ void build_doc_kernel(const float* __restrict__ de, const float* __restrict__ dm,
                                 const float* __restrict__ pos_d,
                                 float* __restrict__ SEQ, float* __restrict__ X,
                                 float* __restrict__ CM)
{
    int bc = blockIdx.x;             // 0..399
    int b = bc / C_CHUNKS, c = bc % C_CHUNKS;
    int tid = threadIdx.x;
    for (int idx = tid; idx < EXT * E_DIM; idx += 256) {
        int j = idx >> 9, e = idx & 511;
        int src = c * CHUNK + j - OVERLAP;
        float v = (src >= 0 && src < D_LEN) ? de[((size_t)b * D_LEN + src) * E_DIM + e] : 0.f;
        size_t o = ((size_t)bc * EXT + j) * E_DIM + e;
        SEQ[o] = v;
        X[o] = v + pos_d[idx];
    }
    for (int j = tid; j < EXT; j += 256) {
        int src = c * CHUNK + j - OVERLAP;
        CM[bc * EXT + j] = (src >= 0 && src < D_LEN) ? dm[b * D_LEN + src] : 0.f;
    }
}

__global__ void build_min_kernel(const float* __restrict__ CM, float* __restrict__ MIN)
{
    int bc = blockIdx.x;
    int b = bc / C_CHUNKS, c = bc % C_CHUNKS;
    __shared__ float psum;
    if (threadIdx.x == 0) {
        float s = 0.f;
        for (int d = 0; d < CHUNK; d++) s += CM[bc * EXT + OVERLAP + d];
        psum = s;
    }
    __syncthreads();
    float pk = (psum != 0.f) ? 1.f : 0.f;
    if (threadIdx.x < CHUNK) {
        MIN[(size_t)b * D_LEN + c * CHUNK + threadIdx.x] =
            CM[bc * EXT + OVERLAP + threadIdx.x] * pk;
    }
}

// ---------------- fused mix + mask + L2-normalize ----------------
__device__ __forceinline__ float blk128_sum(float v, float* red)
{
    for (int o = 16; o > 0; o >>= 1) v += __shfl_xor_sync(0xffffffffu, v, o);
    if ((threadIdx.x & 31) == 0) red[threadIdx.x >> 5] = v;
    __syncthreads();
    return red[0] + red[1] + red[2] + red[3];
}

__global__ void __launch_bounds__(128) mixnorm_q_kernel(
    const float* __restrict__ qe, const float* __restrict__ Xq,
    const float* __restrict__ qm, const float* __restrict__ mixer,
    float* __restrict__ QN)
{
    __shared__ float red[4];
    int r = blockIdx.x;              // 0..239
    float mx = mixer[0];
    float mk = qm[r];
    size_t off = (size_t)r * E_DIM + threadIdx.x * 4;
    float4 s4 = *(const float4*)(qe + off);
    float4 x4 = *(const float4*)(Xq + off);
    float4 v;
    v.x = (mx * s4.x + (1.f - mx) * x4.x) * mk;
    v.y = (mx * s4.y + (1.f - mx) * x4.y) * mk;
    v.z = (mx * s4.z + (1.f - mx) * x4.z) * mk;
    v.w = (mx * s4.w + (1.f - mx) * x4.w) * mk;
    float ss = v.x * v.x + v.y * v.y + v.z * v.z + v.w * v.w;
    float tot = blk128_sum(ss, red);
    float inv = 1.f / (sqrtf(tot) + 1e-13f);
    float4 o = make_float4(v.x * inv, v.y * inv, v.z * inv, v.w * inv);
    *(float4*)(QN + off) = o;
}

__global__ void __launch_bounds__(128) mixnorm_d_kernel(
    const float* __restrict__ SEQ, const float* __restrict__ X,
    const float* __restrict__ CM, const float* __restrict__ mixer,
    float* __restrict__ DN)
{
    __shared__ float red[4];
    int r = blockIdx.x;              // b*2000 + p
    int b = r / D_LEN, p = r % D_LEN;
    int c = p / CHUNK, d = p % CHUNK;
    int srow = (b * C_CHUNKS + c) * EXT + OVERLAP + d;
    float mx = mixer[0];
    float mk = CM[srow];
    size_t off = (size_t)srow * E_DIM + threadIdx.x * 4;
    float4 s4 = *(const float4*)(SEQ + off);
    float4 x4 = *(const float4*)(X + off);
    float4 v;
    v.x = (mx * s4.x + (1.f - mx) * x4.x) * mk;
    v.y = (mx * s4.y + (1.f - mx) * x4.y) * mk;
    v.z = (mx * s4.z + (1.f - mx) * x4.z) * mk;
    v.w = (mx * s4.w + (1.f - mx) * x4.w) * mk;
    float ss = v.x * v.x + v.y * v.y + v.z * v.z + v.w * v.w;
    float tot = blk128_sum(ss, red);
    float inv = 1.f / (sqrtf(tot) + 1e-13f);
    float4 o = make_float4(v.x * inv, v.y * inv, v.z * inv, v.w * inv);
    *(float4*)(DN + (size_t)r * E_DIM + threadIdx.x * 4) = o;
}

// ---------------- cos + RBF kernels -> ACTS[b][q][p][k] ----------------
__global__ void __launch_bounds__(256) acts_kernel(
    const float* __restrict__ QN, const float* __restrict__ DN,
    const float* __restrict__ MIN, const float* __restrict__ mu,
    const float* __restrict__ sigma, float* __restrict__ ACTS)
{
    __shared__ float dn_s[E_DIM];
    __shared__ float mus[NK], sg[NK];
    int r = blockIdx.x;              // b*2000 + p
    int b = r / D_LEN;
    int p = r % D_LEN;
    int tid = threadIdx.x;
    for (int e = tid; e < E_DIM; e += 256) dn_s[e] = DN[(size_t)r * E_DIM + e];
    if (tid < NK) { mus[tid] = mu[tid]; sg[tid] = 0.5f / (sigma[tid] * sigma[tid]); }
    __syncthreads();
    float mn = MIN[r];
    int warp = tid >> 5, lane = tid & 31;
    for (int q = warp; q < Q_LEN; q += 8) {
        const float* qrow = QN + ((size_t)b * Q_LEN + q) * E_DIM;
        float d = 0.f;
        for (int e = lane; e < E_DIM; e += 32) d = fmaf(qrow[e], dn_s[e], d);
        for (int o = 16; o > 0; o >>= 1) d += __shfl_xor_sync(0xffffffffu, d, o);
        if (lane < NK) {
            float df = d - mus[lane];
            float val = expf(-df * df * sg[lane]) * mn;
            ACTS[(((size_t)b * Q_LEN + q) * D_LEN + p) * NK + lane] = val;
        }
    }
}

// ---------------- sliding-window scores ----------------
__global__ void __launch_bounds__(352) score_kernel(
    const float* __restrict__ ACTS, const float* __restrict__ MIN,
    const float* __restrict__ qm, const float* __restrict__ dense_w,
    float* __restrict__ SCORE)
{
    int w = blockIdx.x;              // 0..985
    int b = blockIdx.y;
    int tid = threadIdx.x;
    __shared__ float sat_s[Q_LEN * NK];
    __shared__ float red[NK];
    __shared__ float Lsh;
    if (tid == 0) {
        float L = 0.f;
        for (int j = 0; j < SLIDE; j++)
            if (MIN[(size_t)b * D_LEN + 2 * w + j] != 0.f) L += 1.f;
        Lsh = L;
    }
    __syncthreads();
    if (tid < Q_LEN * NK) {
        int q = tid / NK, k = tid % NK;
        size_t base = (((size_t)b * Q_LEN + q) * D_LEN + 2 * w) * NK + k;
        float pkq = 0.f;
#pragma unroll
        for (int j = 0; j < SLIDE; j++) pkq += ACTS[base + (size_t)j * NK];
        float sat = logf(fmaxf(pkq, 1e-10f)) * qm[b * Q_LEN + q] * (Lsh > 0.f ? 1.f : 0.f);
        sat_s[tid] = sat;
    }
    __syncthreads();
    if (tid < NK) {
        float pk = 0.f;
        for (int q = 0; q < Q_LEN; q++) pk += sat_s[q * NK + tid];
        red[tid] = pk * dense_w[tid];
    }
    __syncthreads();
    if (tid == 0) {
        float s = 0.f;
        for (int k = 0; k < NK; k++) s += red[k];
        if (s == 0.f) s = -9000.f;
        SCORE[b * NWIN + w] = s;
    }
}

// ---------------- topk with suppression + final score ----------------
__global__ void topk_kernel(const float* __restrict__ SCORE,
                            const float* __restrict__ cs, float* __restrict__ out)
{
    int b = blockIdx.x;
    __shared__ float sc[NWIN];
    __shared__ float work[NWIN];
    for (int i = threadIdx.x; i < NWIN; i += blockDim.x) {
        float v = SCORE[b * NWIN + i];
        sc[i] = v;
        work[i] = v;
    }
    __syncthreads();
    if (threadIdx.x == 0) {
        int tops[TOPK];
        for (int t = 0; t < TOPK; t++) {
            int best = 0; float bv = work[0];
            for (int i = 1; i < NWIN; i++)
                if (work[i] > bv) { bv = work[i]; best = i; }
            tops[t] = best;
            for (int i = 0; i < NWIN; i++) {
                int d = i - best; if (d < 0) d = -d;
                if (d < 15) work[i] = -10001.f - (float)t;
            }
        }
        float acc = 0.f;
        const int offs[5] = {0, -1, 1, -2, 2};
        for (int oi = 0; oi < 5; oi++)
            for (int t = 0; t < TOPK; t++) {
                int idx = tops[t] + offs[oi];
                if (idx < 0) idx = 0;
                if (idx > NWIN - 1) idx = NWIN - 1;
                float v = sc[idx];
                if (v <= -9000.f) v = 0.f;
                acc += v * cs[oi * TOPK + t];
            }
        out[b] = acc;
    }
}

// ---------------- host orchestration ----------------
extern "C" void kernel_launch(void* const* d_in, const int* in_sizes, int n_in,
                              void* d_out, int out_size)
{
    const float* qe      = (const float*)d_in[0];
    const float* de      = (const float*)d_in[1];
    const float* qm      = (const float*)d_in[2];
    const float* dm      = (const float*)d_in[3];
    const float* pos_q   = (const float*)d_in[4];
    const float* pos_d   = (const float*)d_in[5];
    const float* Wqkv    = (const float*)d_in[6];
    const float* bqkv    = (const float*)d_in[7];
    const float* Wo      = (const float*)d_in[8];
    const float* bo      = (const float*)d_in[9];
    const float* ln1g    = (const float*)d_in[10];
    const float* ln1b    = (const float*)d_in[11];
    const float* Wff1    = (const float*)d_in[12];
    const float* bff1    = (const float*)d_in[13];
    const float* Wff2    = (const float*)d_in[14];
    const float* bff2    = (const float*)d_in[15];
    const float* ln2g    = (const float*)d_in[16];
    const float* ln2b    = (const float*)d_in[17];
    const float* mixer   = (const float*)d_in[18];
    const float* dense_w = (const float*)d_in[19];
    const float* chunksc = (const float*)d_in[20];
    const float* mu      = (const float*)d_in[21];
    const float* sigma   = (const float*)d_in[22];
    (void)in_sizes; (void)n_in; (void)out_size;

    float *X, *QKV, *O, *T, *F1, *SEQ, *CM, *QN, *DN, *MIN, *ACTS, *SCORE;
    cudaGetSymbolAddress((void**)&X, g_X);
    cudaGetSymbolAddress((void**)&QKV, g_QKV);
    cudaGetSymbolAddress((void**)&O, g_O);
    cudaGetSymbolAddress((void**)&T, g_T);
    cudaGetSymbolAddress((void**)&F1, g_F1);
    cudaGetSymbolAddress((void**)&SEQ, g_SEQ);
    cudaGetSymbolAddress((void**)&CM, g_CM);
    cudaGetSymbolAddress((void**)&QN, g_QN);
    cudaGetSymbolAddress((void**)&DN, g_DN);
    cudaGetSymbolAddress((void**)&MIN, g_MIN);
    cudaGetSymbolAddress((void**)&ACTS, g_ACTS);
    cudaGetSymbolAddress((void**)&SCORE, g_SCORE);

    // ---- build combined input: rows [0,DOC_M) = doc chunks, [DOC_M,TOT_M) = query ----
    build_doc_kernel<<<B_BATCH * C_CHUNKS, 256>>>(de, dm, pos_d, SEQ, X, CM);
    build_query_kernel<<<(QRY_M * E_DIM + 255) / 256, 256>>>(
        qe, pos_q, X + (size_t)DOC_M * E_DIM);

    // ---- single fused transformer over TOT_M rows ----
    {
        int M = TOT_M;
        int gy = (M + BM - 1) / BM;
        for (int l = 0; l < L_LAYERS; l++) {
            const float* Wq  = Wqkv + (size_t)l * 3 * E_DIM * E_DIM;
            const float* bq  = bqkv + (size_t)l * 3 * E_DIM;
            const float* Wol = Wo   + (size_t)l * E_DIM * E_DIM;
            const float* bol = bo   + (size_t)l * E_DIM;
            const float* W1l = Wff1 + (size_t)l * FF_DIM * E_DIM;
            const float* b1l = bff1 + (size_t)l * FF_DIM;
            const float* W2l = Wff2 + (size_t)l * E_DIM * FF_DIM;
            const float* b2l = bff2 + (size_t)l * E_DIM;

            gemm_tf32_nt<<<dim3(3 * E_DIM / BN, gy), 256>>>(
                X, Wq, bq, QKV, M, 3 * E_DIM, E_DIM, 0);
            // doc segment: 400 seqs of S=50
            attn_kernel<<<B_BATCH * C_CHUNKS * H_HEADS, 256>>>(QKV, CM, O, EXT);
            // query segment: 8 seqs of S=30
            attn_kernel<<<B_BATCH * H_HEADS, 256>>>(
                QKV + (size_t)DOC_M * 3 * E_DIM, qm, O + (size_t)DOC_M * E_DIM, Q_LEN);
            gemm_tf32_nt<<<dim3(E_DIM / BN, gy), 256>>>(
                O, Wol, bol, T, M, E_DIM, E_DIM, 0);
            ln_kernel<<<M, 128>>>(X, T, ln1g + (size_t)l * E_DIM, ln1b + (size_t)l * E_DIM);
            gemm_tf32_nt<<<dim3(FF_DIM / BN, gy), 256>>>(
                X, W1l, b1l, F1, M, FF_DIM, E_DIM, 1);
            gemm_tf32_nt<<<dim3(E_DIM / BN, gy), 256>>>(
                F1, W2l, b2l, T, M, E_DIM, FF_DIM, 0);
            ln_kernel<<<M, 128>>>(X, T, ln2g + (size_t)l * E_DIM, ln2b + (size_t)l * E_DIM);
        }
    }

    // ---- mix + normalize ----
    mixnorm_q_kernel<<<QRY_M, 128>>>(qe, X + (size_t)DOC_M * E_DIM, qm, mixer, QN);
    mixnorm_d_kernel<<<B_BATCH * D_LEN, 128>>>(SEQ, X, CM, mixer, DN);
    build_min_kernel<<<B_BATCH * C_CHUNKS, 64>>>(CM, MIN);

    // ---- matching / scoring ----
    acts_kernel<<<B_BATCH * D_LEN, 256>>>(QN, DN, MIN, mu, sigma, ACTS);
    score_kernel<<<dim3(NWIN, B_BATCH), 352>>>(ACTS, MIN, qm, dense_w, SCORE);
    topk_kernel<<<B_BATCH, 256>>>(SCORE, chunksc, (float*)d_out);
}